// round 17
// baseline (speedup 1.0000x reference)
#include <cuda_runtime.h>
#include <cuda_fp16.h>

// DistMult scoring, R16 = R15 (best: 43.1us) minus the smem epilogue.
//   convert: Ah = fp16(A*k), Bh = fp16(B); one thread per 8 floats, __ldcs
//            streaming reads, evict_last 16B stores. (R11 verbatim)
//   score:   2 edges/warp, 16 lanes/edge, direct-LDG gathers (regs=32,
//            occ 90%), HFMA2 dots, packed butterfly reduction, then ONE
//            predicated STG per lane (head/tail scores of an edge pair are
//            contiguous -> 3 store wavefronts/warp, no smem, no barrier).
// out = [pos (E), head (4E), tail (4E)]

#define D 128
#define NEG 4
#define WPB 8            // warps per block (score kernel)
#define EPB (2 * WPB)    // edges per block
#define NROWS 100000

__device__ __align__(16) __half d_Ah[(size_t)NROWS * D];
__device__ __align__(16) __half d_Bh[(size_t)NROWS * D];

__device__ __forceinline__ unsigned h2_bits(__half2 h) {
    return *reinterpret_cast<unsigned*>(&h);
}

// fp32 result of an 8-element fp16 dot; two half2 chains.
__device__ __forceinline__ float dot_h8(uint4 x, uint4 y) {
    const __half2* xa = (const __half2*)&x;
    const __half2* ya = (const __half2*)&y;
    __half2 acc0 = __hmul2(xa[0], ya[0]);
    __half2 acc1 = __hmul2(xa[1], ya[1]);
    acc0 = __hfma2(xa[2], ya[2], acc0);
    acc1 = __hfma2(xa[3], ya[3], acc1);
    acc0 = __hadd2(acc0, acc1);
    return __low2float(acc0) + __high2float(acc0);
}

// 16B register load, L1 non-coherent, L2 evict_last
__device__ __forceinline__ uint4 ldg_resident_u4(const uint4* p, unsigned long long pol) {
    uint4 r;
    asm volatile(
        "ld.global.nc.L2::cache_hint.v4.u32 {%0,%1,%2,%3}, [%4], %5;"
        : "=r"(r.x), "=r"(r.y), "=r"(r.z), "=r"(r.w)
        : "l"(p), "l"(pol));
    return r;
}

// ---------------- pass 1: fp32 -> fp16 conversion (R11 verbatim) --------
__global__ void __launch_bounds__(256) convert_kernel(
    const float4* __restrict__ A4,
    const float4* __restrict__ B4,
    const float*  __restrict__ K,
    int nA8, int nB8)
{
    int i = blockIdx.x * blockDim.x + threadIdx.x;

    unsigned long long pol;  // keep fp16 tables L2-resident
    asm volatile("createpolicy.fractional.L2::evict_last.b64 %0, 1.0;" : "=l"(pol));

    if (i < nA8) {
        float4 v0 = __ldcs(A4 + 2 * (size_t)i);
        float4 v1 = __ldcs(A4 + 2 * (size_t)i + 1);
        float4 k0 = __ldg((const float4*)K + ((2 * i) & 31));
        float4 k1 = __ldg((const float4*)K + ((2 * i + 1) & 31));
        __half2 h0 = __floats2half2_rn(v0.x * k0.x, v0.y * k0.y);
        __half2 h1 = __floats2half2_rn(v0.z * k0.z, v0.w * k0.w);
        __half2 h2 = __floats2half2_rn(v1.x * k1.x, v1.y * k1.y);
        __half2 h3 = __floats2half2_rn(v1.z * k1.z, v1.w * k1.w);
        unsigned u0 = h2_bits(h0), u1 = h2_bits(h1);
        unsigned u2 = h2_bits(h2), u3 = h2_bits(h3);
        uint4* dst = reinterpret_cast<uint4*>(d_Ah) + i;
        asm volatile("st.global.L2::cache_hint.v4.u32 [%0], {%1,%2,%3,%4}, %5;"
                     :: "l"(dst), "r"(u0), "r"(u1), "r"(u2), "r"(u3), "l"(pol));
    } else if (i < nA8 + nB8) {
        int j = i - nA8;
        float4 v0 = __ldcs(B4 + 2 * (size_t)j);
        float4 v1 = __ldcs(B4 + 2 * (size_t)j + 1);
        __half2 h0 = __floats2half2_rn(v0.x, v0.y);
        __half2 h1 = __floats2half2_rn(v0.z, v0.w);
        __half2 h2 = __floats2half2_rn(v1.x, v1.y);
        __half2 h3 = __floats2half2_rn(v1.z, v1.w);
        unsigned u0 = h2_bits(h0), u1 = h2_bits(h1);
        unsigned u2 = h2_bits(h2), u3 = h2_bits(h3);
        uint4* dst = reinterpret_cast<uint4*>(d_Bh) + j;
        asm volatile("st.global.L2::cache_hint.v4.u32 [%0], {%1,%2,%3,%4}, %5;"
                     :: "l"(dst), "r"(u0), "r"(u1), "r"(u2), "r"(u3), "l"(pol));
    }
}

// ---------------- pass 2: gather-dot scoring (direct LDG, direct STG) ---
__global__ void __launch_bounds__(32 * WPB) score_kernel(
    const int* __restrict__ ep,    // [2, E]
    const int* __restrict__ hb,    // [E, 4]
    const int* __restrict__ tb,    // [E, 4]
    float*     __restrict__ out,   // [9E]
    int E)
{
    int w     = threadIdx.x >> 5;
    int lane  = threadIdx.x & 31;
    int laneh = lane & 15;
    int side  = lane >> 4;
    int e     = 2 * (blockIdx.x * WPB + w) + side;

    unsigned long long pol;
    asm volatile("createpolicy.fractional.L2::evict_last.b64 %0, 1.0;" : "=l"(pol));

    if (e < E) {
        int h = __ldg(&ep[e]);
        int t = __ldg(&ep[E + e]);
        int4 hbi = __ldg((const int4*)(hb) + e);
        int4 tbi = __ldg((const int4*)(tb) + e);
        int hidx[NEG] = {hbi.x, hbi.y, hbi.z, hbi.w};
        int tidx[NEG] = {tbi.x, tbi.y, tbi.z, tbi.w};

        const uint4* Ah4 = (const uint4*)d_Ah;  // 16 uint4 per 128-half row
        const uint4* Bh4 = (const uint4*)d_Bh;

        // issue all 10 row gathers back-to-back (MLP=10, fp16 rows: 40 regs)
        uint4 av = ldg_resident_u4(Ah4 + (size_t)h * (D / 8) + laneh, pol);
        uint4 bv = ldg_resident_u4(Bh4 + (size_t)t * (D / 8) + laneh, pol);
        uint4 ha[NEG], tv[NEG];
#pragma unroll
        for (int j = 0; j < NEG; j++) {
            ha[j] = ldg_resident_u4(Ah4 + (size_t)hidx[j] * (D / 8) + laneh, pol);
            tv[j] = ldg_resident_u4(Bh4 + (size_t)tidx[j] * (D / 8) + laneh, pol);
        }

        float pos = dot_h8(av, bv);
        float hs[NEG], ts[NEG];
#pragma unroll
        for (int j = 0; j < NEG; j++) {
            hs[j] = dot_h8(ha[j], bv);
            ts[j] = dot_h8(av, tv[j]);
        }

        // --- packed butterfly reduction over the 16-lane half ---
        pos += __shfl_xor_sync(0xFFFFFFFFu, pos, 8);
#pragma unroll
        for (int j = 0; j < NEG; j++) {
            hs[j] += __shfl_xor_sync(0xFFFFFFFFu, hs[j], 8);
            ts[j] += __shfl_xor_sync(0xFFFFFFFFu, ts[j], 8);
        }
        bool hi = laneh >= 8;
        float r0 = hi ? hs[0] : pos;
        float r1 = hi ? hs[2] : hs[1];
        float r2 = hi ? ts[0] : hs[3];
        float r3 = hi ? ts[2] : ts[1];
        float r4 = ts[3];
#pragma unroll
        for (int m = 4; m >= 1; m >>= 1) {
            r0 += __shfl_xor_sync(0xFFFFFFFFu, r0, m);
            r1 += __shfl_xor_sync(0xFFFFFFFFu, r1, m);
            r2 += __shfl_xor_sync(0xFFFFFFFFu, r2, m);
            r3 += __shfl_xor_sync(0xFFFFFFFFu, r3, m);
            r4 += __shfl_xor_sync(0xFFFFFFFFu, r4, m);
        }

        // lane -> score: lo lanes (laneh 0..4) hold {pos,hs1,hs3,ts1,ts3},
        // hi lanes (laneh 8..11) hold {hs0,hs2,ts0,ts2}; idx = 2*lh + hibit.
        int lh = laneh & 7;
        float val = r4;
        if (lh == 0) val = r0;
        else if (lh == 1) val = r1;
        else if (lh == 2) val = r2;
        else if (lh == 3) val = r3;
        int idx = 2 * lh + (laneh >> 3);
        bool active = hi ? (lh < 4) : (lh < 5);
        // idx: 0=pos, 1..4=hs0..hs3, 5..8=ts0..ts3
        if (active) {
            size_t addr;
            if (idx == 0)
                addr = (size_t)e;                                   // pos region
            else if (idx < 5)
                addr = (size_t)E + 4 * (size_t)e + (idx - 1);        // head region
            else
                addr = (size_t)E * 5 + 4 * (size_t)e + (idx - 5);    // tail region
            __stcs(&out[addr], val);
            // per warp: head floats of edges (e,e+1) are 8 contiguous -> 1 wf,
            // tail same -> 1 wf, pos 2 floats -> 1 wf. 3 store wavefronts.
        }
    }
}

extern "C" void kernel_launch(void* const* d_in, const int* in_sizes, int n_in,
                              void* d_out, int out_size) {
    const float* emb_A = (const float*)d_in[0];
    const float* emb_B = (const float*)d_in[1];
    const float* rel_k = (const float*)d_in[2];
    const int*   ep    = (const int*)d_in[3];
    const int*   hb    = (const int*)d_in[4];
    const int*   tb    = (const int*)d_in[5];
    float*       out   = (float*)d_out;

    int E   = in_sizes[3] / 2;
    int nA8 = in_sizes[0] / 8;
    int nB8 = in_sizes[1] / 8;

    int ntot = nA8 + nB8;
    convert_kernel<<<(ntot + 255) / 256, 256>>>(
        (const float4*)emb_A, (const float4*)emb_B, rel_k, nA8, nB8);

    int grid = (E + EPB - 1) / EPB;
    score_kernel<<<grid, 32 * WPB>>>(ep, hb, tb, out, E);
}